// round 8
// baseline (speedup 1.0000x reference)
#include <cuda_runtime.h>

// Rows / W2-columns that actually matter (derived from the reshape-select in the
// reference; validated by passing R2/R5/R7 kernels):
//   branch3: slot i<64  -> batch row 64*i,      W2 column 1
//   branch4: slot 64+j  -> rows {0,682,1365,2048,2730,3413}, cols {65,69,67,65,69,67}
__constant__ int c_r4[6] = {0, 682, 1365, 2048, 2730, 3413};
__constant__ int c_c4[6] = {65, 69, 67, 65, 69, 67};

#define SEG3_END   409600
#define BIAS_END   409664

// ---------------------------------------------------------------------------
// 70 blocks, one per slot. Single __syncthreads on the critical path:
// all parameter data is prefetched into shared CONCURRENTLY with the dot
// product's global loads; after one bar every warp redundantly reduces the
// 16 partials so every thread holds the result with no further sync.
// ---------------------------------------------------------------------------
__global__ void __launch_bounds__(512) fused_kernel(const float* __restrict__ inp,
                                                    const float* __restrict__ W1,
                                                    const float* __restrict__ b1,
                                                    const float* __restrict__ W2,
                                                    const float* __restrict__ b2,
                                                    const float* __restrict__ W3a,
                                                    const float* __restrict__ b3a,
                                                    const float* __restrict__ W3b,
                                                    const float* __restrict__ b3b,
                                                    const float* __restrict__ W4a,
                                                    const float* __restrict__ b4a,
                                                    const float* __restrict__ W4b,
                                                    const float* __restrict__ b4b,
                                                    float* __restrict__ out) {
    __shared__ float warp_sums[16];
    __shared__ float sh_par[5];                    // b1, W2[c], b2[c], Wxa, bxa
    __shared__ __align__(16) float sh_w[516];      // W3b[80] or W4b[513]
    __shared__ __align__(16) float sh_b[516];      // b3b[80] or b4b[513]

    int slot = blockIdx.x;
    int tid  = threadIdx.x;
    int lane = tid & 31;
    int wid  = tid >> 5;

    bool is3 = (slot < 64);
    int row = is3 ? (slot * 64) : c_r4[slot - 64];

    const float4* x = reinterpret_cast<const float4*>(inp + (size_t)row * 6400);
    const float4* w = reinterpret_cast<const float4*>(W1);

    // --- Issue ALL loads up front: dot operands + parameter prefetch ---
    float4 a0 = x[tid];
    float4 w0 = w[tid];
    float4 a1 = x[tid + 512];
    float4 w1 = w[tid + 512];
    float4 a2 = x[tid + 1024];
    float4 w2 = w[tid + 1024];

    // Parameter prefetch (independent loads, overlap with the above).
    if (is3) {
        if (tid < 80) {
            sh_w[tid] = __ldg(W3b + tid);
            sh_b[tid] = __ldg(b3b + tid);
        }
    } else {
        for (int k = tid; k < 513; k += 512) {
            sh_w[k] = __ldg(W4b + k);
            sh_b[k] = __ldg(b4b + k);
        }
    }
    if (tid == 256) {
        int c = is3 ? 1 : c_c4[slot - 64];
        sh_par[0] = __ldg(b1);
        sh_par[1] = __ldg(W2 + c);
        sh_par[2] = __ldg(b2 + c);
        sh_par[3] = is3 ? __ldg(W3a) : __ldg(W4a);
        sh_par[4] = is3 ? __ldg(b3a) : __ldg(b4a);
    }

    float sum = 0.f;
    sum = fmaf(a0.x, w0.x, sum); sum = fmaf(a0.y, w0.y, sum);
    sum = fmaf(a0.z, w0.z, sum); sum = fmaf(a0.w, w0.w, sum);
    sum = fmaf(a1.x, w1.x, sum); sum = fmaf(a1.y, w1.y, sum);
    sum = fmaf(a1.z, w1.z, sum); sum = fmaf(a1.w, w1.w, sum);
    sum = fmaf(a2.x, w2.x, sum); sum = fmaf(a2.y, w2.y, sum);
    sum = fmaf(a2.z, w2.z, sum); sum = fmaf(a2.w, w2.w, sum);
    if (tid < 64) {
        float4 a3 = x[tid + 1536];
        float4 w3 = w[tid + 1536];
        sum = fmaf(a3.x, w3.x, sum); sum = fmaf(a3.y, w3.y, sum);
        sum = fmaf(a3.z, w3.z, sum); sum = fmaf(a3.w, w3.w, sum);
    }

    // Warp-level reduce.
    #pragma unroll
    for (int off = 16; off > 0; off >>= 1)
        sum += __shfl_down_sync(0xffffffffu, sum, off);
    if (lane == 0) warp_sums[wid] = sum;

    __syncthreads();   // the ONLY block-wide sync

    // Every warp redundantly reduces the 16 partials; broadcast via shuffle.
    float t = (lane < 16) ? warp_sums[lane] : 0.f;
    #pragma unroll
    for (int off = 8; off > 0; off >>= 1)
        t += __shfl_down_sync(0xffffffffu, t, off);
    float total = __shfl_sync(0xffffffffu, t, 0);

    // Scalar hyper-MLP chain, computed by every thread from shared params.
    float s  = fmaxf(total + sh_par[0], 0.f);
    float x1 = fmaxf(fmaf(s, sh_par[1], sh_par[2]), 0.f);
    float a  = fmaxf(fmaf(x1, sh_par[3], sh_par[4]), 0.f);

    // --- Output streaming, values computed inline from prefetched shared ---
    if (is3) {
        float* base = out + slot * 80;
        // 80 tiles x 20 float4 = 1600 float4 stores
        #pragma unroll 4
        for (int m = tid; m < 1600; m += 512) {
            int p  = m / 20;
            int k4 = (m - p * 20) * 4;
            float4 wv = *reinterpret_cast<const float4*>(sh_w + k4);
            float4 bv = *reinterpret_cast<const float4*>(sh_b + k4);
            float4 v;
            v.x = fmaxf(fmaf(a, wv.x, bv.x), 0.f);
            v.y = fmaxf(fmaf(a, wv.y, bv.y), 0.f);
            v.z = fmaxf(fmaf(a, wv.z, bv.z), 0.f);
            v.w = fmaxf(fmaf(a, wv.w, bv.w), 0.f);
            *reinterpret_cast<float4*>(base + p * 5120 + k4) = v;
        }
    } else {
        int j = slot - 64;
        float* base = out + BIAS_END + j * 513;
        for (int k = tid; k < 513; k += 512)
            base[k] = fmaxf(fmaf(a, sh_w[k], sh_b[k]), 0.f);
        if (j == 0 && tid < 64)
            out[SEG3_END + tid] = 0.f;
    }
}

extern "C" void kernel_launch(void* const* d_in, const int* in_sizes, int n_in,
                              void* d_out, int out_size) {
    const float* inputs = (const float*)d_in[0];
    const float* W1  = (const float*)d_in[1];
    const float* b1  = (const float*)d_in[2];
    const float* W2  = (const float*)d_in[3];
    const float* b2  = (const float*)d_in[4];
    const float* W3a = (const float*)d_in[5];
    const float* b3a = (const float*)d_in[6];
    const float* W3b = (const float*)d_in[7];
    const float* b3b = (const float*)d_in[8];
    const float* W4a = (const float*)d_in[9];
    const float* b4a = (const float*)d_in[10];
    const float* W4b = (const float*)d_in[11];
    const float* b4b = (const float*)d_in[12];
    float* out = (float*)d_out;

    fused_kernel<<<70, 512>>>(inputs, W1, b1, W2, b2, W3a, b3a, W3b, b3b,
                              W4a, b4a, W4b, b4b, out);
}

// round 9
// speedup vs baseline: 1.1389x; 1.1389x over previous
#include <cuda_runtime.h>

// Rows / W2-columns that actually matter (derived from the reshape-select in the
// reference; validated by passing R2/R5/R7/R8 kernels):
//   branch3: slot i<64  -> batch row 64*i,      W2 column 1
//   branch4: slot 64+j  -> rows {0,682,1365,2048,2730,3413}, cols {65,69,67,65,69,67}
__constant__ int c_r4[6] = {0, 682, 1365, 2048, 2730, 3413};
__constant__ int c_c4[6] = {65, 69, 67, 65, 69, 67};

#define SEG3_END   409600
#define BIAS_END   409664

// ---------------------------------------------------------------------------
// Grid = 134 blocks, one wave:
//   blocks 0..127  : branch-3, slot = b>>1, half = b&1. Both halves compute
//                    the dot redundantly (loads dedup in L2); each stores 40
//                    of the 80 output tiles (800 STG.128).
//   blocks 128..133: branch-4 (6 x 513) + 64-float zero gap.
// Single __syncthreads on the critical path; all params prefetched into
// shared concurrently with the dot's global loads; post-bar every warp
// redundantly reduces the 16 partials (no second bar, no round trips).
// ---------------------------------------------------------------------------
__global__ void __launch_bounds__(512) fused_kernel(const float* __restrict__ inp,
                                                    const float* __restrict__ W1,
                                                    const float* __restrict__ b1,
                                                    const float* __restrict__ W2,
                                                    const float* __restrict__ b2,
                                                    const float* __restrict__ W3a,
                                                    const float* __restrict__ b3a,
                                                    const float* __restrict__ W3b,
                                                    const float* __restrict__ b3b,
                                                    const float* __restrict__ W4a,
                                                    const float* __restrict__ b4a,
                                                    const float* __restrict__ W4b,
                                                    const float* __restrict__ b4b,
                                                    float* __restrict__ out) {
    __shared__ float warp_sums[16];
    __shared__ float sh_par[5];                    // b1, W2[c], b2[c], Wxa, bxa
    __shared__ __align__(16) float sh_w[516];      // W3b[80] or W4b[513]
    __shared__ __align__(16) float sh_b[516];      // b3b[80] or b4b[513]

    int b    = blockIdx.x;
    int tid  = threadIdx.x;
    int lane = tid & 31;
    int wid  = tid >> 5;

    bool is3 = (b < 128);
    int slot, half = 0, row;
    if (is3) {
        slot = b >> 1;
        half = b & 1;
        row  = slot * 64;
    } else {
        slot = 64 + (b - 128);
        row  = c_r4[b - 128];
    }

    const float4* x = reinterpret_cast<const float4*>(inp + (size_t)row * 6400);
    const float4* w = reinterpret_cast<const float4*>(W1);

    // --- Issue ALL loads up front: dot operands + parameter prefetch ---
    float4 a0 = x[tid];
    float4 w0 = w[tid];
    float4 a1 = x[tid + 512];
    float4 w1 = w[tid + 512];
    float4 a2 = x[tid + 1024];
    float4 w2 = w[tid + 1024];

    // Parameter prefetch (independent loads; overlap with the above).
    if (is3) {
        if (tid < 80) {
            sh_w[tid] = __ldg(W3b + tid);
            sh_b[tid] = __ldg(b3b + tid);
        }
    } else {
        for (int k = tid; k < 513; k += 512) {
            sh_w[k] = __ldg(W4b + k);
            sh_b[k] = __ldg(b4b + k);
        }
    }
    if (tid == 256) {
        int c = is3 ? 1 : c_c4[slot - 64];
        sh_par[0] = __ldg(b1);
        sh_par[1] = __ldg(W2 + c);
        sh_par[2] = __ldg(b2 + c);
        sh_par[3] = is3 ? __ldg(W3a) : __ldg(W4a);
        sh_par[4] = is3 ? __ldg(b3a) : __ldg(b4a);
    }

    float sum = 0.f;
    sum = fmaf(a0.x, w0.x, sum); sum = fmaf(a0.y, w0.y, sum);
    sum = fmaf(a0.z, w0.z, sum); sum = fmaf(a0.w, w0.w, sum);
    sum = fmaf(a1.x, w1.x, sum); sum = fmaf(a1.y, w1.y, sum);
    sum = fmaf(a1.z, w1.z, sum); sum = fmaf(a1.w, w1.w, sum);
    sum = fmaf(a2.x, w2.x, sum); sum = fmaf(a2.y, w2.y, sum);
    sum = fmaf(a2.z, w2.z, sum); sum = fmaf(a2.w, w2.w, sum);
    if (tid < 64) {
        float4 a3 = x[tid + 1536];
        float4 w3 = w[tid + 1536];
        sum = fmaf(a3.x, w3.x, sum); sum = fmaf(a3.y, w3.y, sum);
        sum = fmaf(a3.z, w3.z, sum); sum = fmaf(a3.w, w3.w, sum);
    }

    // Warp-level reduce.
    #pragma unroll
    for (int off = 16; off > 0; off >>= 1)
        sum += __shfl_down_sync(0xffffffffu, sum, off);
    if (lane == 0) warp_sums[wid] = sum;

    __syncthreads();   // the ONLY block-wide sync

    // Every warp redundantly reduces the 16 partials; broadcast via shuffle.
    float t = (lane < 16) ? warp_sums[lane] : 0.f;
    #pragma unroll
    for (int off = 8; off > 0; off >>= 1)
        t += __shfl_down_sync(0xffffffffu, t, off);
    float total = __shfl_sync(0xffffffffu, t, 0);

    // Scalar hyper-MLP chain, computed by every thread from shared params.
    float s  = fmaxf(total + sh_par[0], 0.f);
    float x1 = fmaxf(fmaf(s, sh_par[1], sh_par[2]), 0.f);
    float a  = fmaxf(fmaf(x1, sh_par[3], sh_par[4]), 0.f);

    // --- Output streaming, values computed inline from prefetched shared ---
    if (is3) {
        float* base = out + slot * 80;
        int p_base = half * 40;
        // 40 tiles x 20 float4 = 800 float4 stores over 512 threads
        #pragma unroll
        for (int m = tid; m < 800; m += 512) {
            int p  = p_base + m / 20;
            int k4 = (m % 20) * 4;
            float4 wv = *reinterpret_cast<const float4*>(sh_w + k4);
            float4 bv = *reinterpret_cast<const float4*>(sh_b + k4);
            float4 v;
            v.x = fmaxf(fmaf(a, wv.x, bv.x), 0.f);
            v.y = fmaxf(fmaf(a, wv.y, bv.y), 0.f);
            v.z = fmaxf(fmaf(a, wv.z, bv.z), 0.f);
            v.w = fmaxf(fmaf(a, wv.w, bv.w), 0.f);
            *reinterpret_cast<float4*>(base + p * 5120 + k4) = v;
        }
    } else {
        int j = slot - 64;
        float* base = out + BIAS_END + j * 513;
        for (int k = tid; k < 513; k += 512)
            base[k] = fmaxf(fmaf(a, sh_w[k], sh_b[k]), 0.f);
        if (j == 0 && tid < 64)
            out[SEG3_END + tid] = 0.f;
    }
}

extern "C" void kernel_launch(void* const* d_in, const int* in_sizes, int n_in,
                              void* d_out, int out_size) {
    const float* inputs = (const float*)d_in[0];
    const float* W1  = (const float*)d_in[1];
    const float* b1  = (const float*)d_in[2];
    const float* W2  = (const float*)d_in[3];
    const float* b2  = (const float*)d_in[4];
    const float* W3a = (const float*)d_in[5];
    const float* b3a = (const float*)d_in[6];
    const float* W3b = (const float*)d_in[7];
    const float* b3b = (const float*)d_in[8];
    const float* W4a = (const float*)d_in[9];
    const float* b4a = (const float*)d_in[10];
    const float* W4b = (const float*)d_in[11];
    const float* b4b = (const float*)d_in[12];
    float* out = (float*)d_out;

    fused_kernel<<<134, 512>>>(inputs, W1, b1, W2, b2, W3a, b3a, W3b, b3b,
                               W4a, b4a, W4b, b4b, out);
}